// round 2
// baseline (speedup 1.0000x reference)
#include <cuda_runtime.h>
#include <math.h>

// Problem constants
#define Bq   16
#define Sq   2048
#define Hq   1024
#define Nq   128
#define NROWS (Bq * Nq)      // 2048 rows
#define KX   (5 * Hq)        // 5120: [L0|L1|G0|G1|Init]

// ---------------- scratch (static __device__, no allocation) ----------------
__device__ float g_X[(size_t)NROWS * KX];   // 40 MB: per-row concatenated operand
__device__ float g_wfT[Hq * Hq];            // w_f transposed to [k][h]
__device__ float g_alpha[NROWS];            // alpha_j (masked)
__device__ int   g_perm[NROWS];             // per-batch sorted order (by number, stable)
__device__ int   g_runstart[NROWS];         // 1 at start of equal-value run
__device__ float g_invD[Bq];                // 1 / max(n_valid-1, 1)
__device__ int   g_rowmap[NROWS + 128];     // rows grouped by resp_i, -1 = pad
__device__ int   g_meta[2];                 // {start1, totalTiles}

// ---------------- K0: transpose w_f [h][k] -> g_wfT [k][h] ----------------
__global__ void k_transpose(const float* __restrict__ wf) {
    __shared__ float t[32][33];
    int x0 = blockIdx.x * 32, y0 = blockIdx.y * 32;
    int tx = threadIdx.x, ty = threadIdx.y;          // (32, 8)
    #pragma unroll
    for (int r = 0; r < 32; r += 8)
        t[ty + r][tx] = wf[(size_t)(y0 + ty + r) * Hq + x0 + tx];
    __syncthreads();
    #pragma unroll
    for (int r = 0; r < 32; r += 8)
        g_wfT[(size_t)(x0 + ty + r) * Hq + y0 + tx] = t[tx][ty + r];
}

// ---------------- K1: gather Init rows + alpha = sigmoid(Init . w_alpha + b) --
__global__ void k_gather(const float* __restrict__ we, const int* __restrict__ ids,
                         const float* __restrict__ w_alpha, const float* __restrict__ b_alpha) {
    int m = blockIdx.x;                      // global row (b*128+n)
    int b = m >> 7;
    int id = ids[m];
    int idc = min(max(id, 0), Sq - 1);
    const float4* src = (const float4*)(we + ((size_t)b * Sq + idc) * Hq);
    float4* dst = (float4*)(g_X + (size_t)m * KX + 4 * Hq);
    const float4* wa = (const float4*)w_alpha;
    float part = 0.f;
    for (int t = threadIdx.x; t < Hq / 4; t += blockDim.x) {
        float4 v = src[t];
        dst[t] = v;
        float4 w = wa[t];
        part += v.x * w.x + v.y * w.y + v.z * w.z + v.w * w.w;
    }
    __shared__ float red[128];
    red[threadIdx.x] = part;
    __syncthreads();
    for (int s = 64; s > 0; s >>= 1) {
        if (threadIdx.x < s) red[threadIdx.x] += red[threadIdx.x + s];
        __syncthreads();
    }
    if (threadIdx.x == 0) {
        float a = 1.f / (1.f + expf(-(red[0] + b_alpha[0])));
        g_alpha[m] = (id >= 0) ? a : 0.f;    // mask folded into alpha
    }
}

// ---------------- K2: per-batch stable sort rank + run starts + denom --------
__global__ void k_rank(const float* __restrict__ numbers, const int* __restrict__ ids) {
    int b = blockIdx.x, i = threadIdx.x;     // 128 threads = 128 nodes
    __shared__ float num[128];
    __shared__ int perm[128];
    __shared__ int validCnt;
    int id = ids[b * 128 + i];
    float x = numbers[b * 128 + i];
    num[i] = x;
    if (i == 0) validCnt = 0;
    __syncthreads();
    int p = 0;
    #pragma unroll 4
    for (int j = 0; j < 128; j++) {
        float y = num[j];
        p += (y < x) || (y == x && j < i);   // stable total order
    }
    perm[p] = i;
    atomicAdd(&validCnt, (id >= 0) ? 1 : 0);
    __syncthreads();
    g_perm[b * 128 + p] = i;
    int node = perm[i];
    int prev = (i > 0) ? perm[i - 1] : 0;
    g_runstart[b * 128 + i] = (i == 0) || (num[node] != num[prev]);
    if (i == 0) g_invD[b] = 1.f / (float)max(validCnt - 1, 1);
}

// ---------------- K3: group rows by resp_i (deterministic scan, 1 block) -----
__global__ void k_group(const int* __restrict__ resp) {
    __shared__ int cls[NROWS];
    __shared__ int offs0[257];
    __shared__ int tcount[256];
    int t = threadIdx.x;                     // 256 threads
    for (int m = t; m < NROWS; m += 256) cls[m] = (resp[m] == 1) ? 1 : 0;
    __syncthreads();
    int c0 = 0;
    #pragma unroll
    for (int k = 0; k < 8; k++) c0 += (cls[t * 8 + k] == 0);
    tcount[t] = c0;
    __syncthreads();
    if (t == 0) {
        int s = 0;
        for (int q = 0; q < 256; q++) { offs0[q] = s; s += tcount[q]; }
        offs0[256] = s;
    }
    __syncthreads();
    int count0 = offs0[256];
    int start1 = ((count0 + 127) / 128) * 128;
    int total1 = NROWS - count0;
    int totalTiles = (start1 + total1 + 127) / 128;
    for (int m = t; m < NROWS + 128; m += 256) g_rowmap[m] = -1;
    __syncthreads();
    int p0 = offs0[t];
    int p1 = start1 + (t * 8 - offs0[t]);
    #pragma unroll
    for (int k = 0; k < 8; k++) {
        int m = t * 8 + k;
        if (cls[m] == 0) g_rowmap[p0++] = m; else g_rowmap[p1++] = m;
    }
    if (t == 0) { g_meta[0] = start1; g_meta[1] = totalTiles; }
}

// ---------------- K4: prefix sums -> X slots 0..3 = [L0 L1 G0 G1]*invD -------
__global__ void k_prefix(const int* __restrict__ resp) {
    int b = blockIdx.x;
    int h = blockIdx.y * 256 + threadIdx.x;  // grid.y = 4 -> 1024 h-lanes
    __shared__ float alpha_s[128];
    __shared__ int perm_s[128], rs_s[128], resp_s[128];
    int t = threadIdx.x;
    if (t < 128) {
        alpha_s[t] = g_alpha[b * 128 + t];
        perm_s[t]  = g_perm[b * 128 + t];
        rs_s[t]    = g_runstart[b * 128 + t];
        resp_s[t]  = resp[b * 128 + t];
    }
    __syncthreads();
    float invD = g_invD[b];
    const float* Xb = g_X + (size_t)b * 128 * KX;
    // pass 1: class totals
    float T0 = 0.f, T1 = 0.f;
    for (int i = 0; i < 128; i++) {
        float u = alpha_s[i] * Xb[(size_t)i * KX + 4 * Hq + h];
        if (resp_s[i]) T1 += u; else T0 += u;
    }
    // pass 2: walk sorted order; snapshot at run starts = strict-less prefix
    float a0 = 0.f, a1 = 0.f, s0 = 0.f, s1 = 0.f;
    for (int p = 0; p < 128; p++) {
        int i = perm_s[p];
        if (rs_s[p]) { s0 = a0; s1 = a1; }
        float u = alpha_s[i] * Xb[(size_t)i * KX + 4 * Hq + h];
        int r = resp_s[i];
        float L0 = s0, L1 = s1;
        float G0 = T0 - L0 - (r ? 0.f : u);
        float G1 = T1 - L1 - (r ? u : 0.f);
        float* Xi = g_X + (size_t)(b * 128 + i) * KX;
        Xi[0 * Hq + h] = L0 * invD;
        Xi[1 * Hq + h] = L1 * invD;
        Xi[2 * Hq + h] = G0 * invD;
        Xi[3 * Hq + h] = G1 * invD;
        if (r) a1 += u; else a0 += u;
    }
}

// ---------------- K5: fused GEMM  out = relu(X @ Wsel(ri)^T + b_f) -----------
// X row: [L0 L1 G0 G1 Init] (K=5120). Weight blocks per slot (all [k][h]):
//   slot0 -> W_{4+2ri}, slot1 -> W_{5+2ri}, slot2 -> W_{2ri}, slot3 -> W_{2ri+1}, slot4 -> w_f^T
#define BM 128
#define BN 128
#define BK 16

__global__ __launch_bounds__(256) void k_gemm(const float* __restrict__ Wr,
                                              const float* __restrict__ b_f,
                                              float* __restrict__ out) {
    int by = blockIdx.y, bx = blockIdx.x;
    int start1 = g_meta[0];
    int totalTiles = g_meta[1];
    if (by >= totalTiles) return;
    int ri = (by * BM >= start1) ? 1 : 0;
    const float* wbase[5];
    wbase[0] = Wr + (size_t)(4 + 2 * ri) * Hq * Hq;
    wbase[1] = Wr + (size_t)(5 + 2 * ri) * Hq * Hq;
    wbase[2] = Wr + (size_t)(2 * ri)     * Hq * Hq;
    wbase[3] = Wr + (size_t)(2 * ri + 1) * Hq * Hq;
    wbase[4] = g_wfT;

    __shared__ float As[BK][BM];
    __shared__ float Bs[BK][BN];
    __shared__ int rows[BM];
    int tid = threadIdx.x;
    for (int r = tid; r < BM; r += 256) rows[r] = g_rowmap[by * BM + r];
    __syncthreads();

    float acc[8][8] = {};
    int ty = tid / 16, tx = tid % 16;

    for (int kk = 0; kk < KX; kk += BK) {
        int slot = kk >> 10;
        int hh = kk & 1023;
        // A tile: 128 rows x 16 k  (512 float4s, 2 per thread)
        #pragma unroll
        for (int l = 0; l < 2; l++) {
            int f4 = tid + l * 256;
            int row = f4 >> 2;
            int kp = (f4 & 3) * 4;
            int grow = rows[row];
            float4 v = make_float4(0.f, 0.f, 0.f, 0.f);
            if (grow >= 0) v = *(const float4*)(g_X + (size_t)grow * KX + kk + kp);
            As[kp + 0][row] = v.x; As[kp + 1][row] = v.y;
            As[kp + 2][row] = v.z; As[kp + 3][row] = v.w;
        }
        // B tile: 128 cols x 16 h
        const float* wb = wbase[slot];
        #pragma unroll
        for (int l = 0; l < 2; l++) {
            int f4 = tid + l * 256;
            int col = f4 >> 2;
            int kp = (f4 & 3) * 4;
            float4 v = *(const float4*)(wb + (size_t)(bx * BN + col) * Hq + hh + kp);
            Bs[kp + 0][col] = v.x; Bs[kp + 1][col] = v.y;
            Bs[kp + 2][col] = v.z; Bs[kp + 3][col] = v.w;
        }
        __syncthreads();
        #pragma unroll
        for (int k = 0; k < BK; k++) {
            float a[8], bb[8];
            #pragma unroll
            for (int j = 0; j < 8; j++) a[j]  = As[k][ty * 8 + j];
            #pragma unroll
            for (int j = 0; j < 8; j++) bb[j] = Bs[k][tx * 8 + j];
            #pragma unroll
            for (int i2 = 0; i2 < 8; i2++)
                #pragma unroll
                for (int j2 = 0; j2 < 8; j2++)
                    acc[i2][j2] += a[i2] * bb[j2];
        }
        __syncthreads();
    }

    #pragma unroll
    for (int i2 = 0; i2 < 8; i2++) {
        int grow = rows[ty * 8 + i2];
        if (grow < 0) continue;
        float* orow = out + (size_t)grow * Hq + bx * BN;
        #pragma unroll
        for (int j2 = 0; j2 < 8; j2++) {
            int col = tx * 8 + j2;
            float v = acc[i2][j2] + b_f[bx * BN + col];
            orow[col] = fmaxf(v, 0.f);
        }
    }
}

// ---------------- launch ----------------
extern "C" void kernel_launch(void* const* d_in, const int* in_sizes, int n_in,
                              void* d_out, int out_size) {
    const float* word_emb  = (const float*)d_in[0];
    const int*   num_ids   = (const int*)  d_in[1];
    const int*   is_resp   = (const int*)  d_in[2];
    const float* numbers   = (const float*)d_in[3];
    const float* w_alpha   = (const float*)d_in[4];
    const float* b_alpha   = (const float*)d_in[5];
    const float* w_f       = (const float*)d_in[6];
    const float* b_f       = (const float*)d_in[7];
    const float* W_r       = (const float*)d_in[8];
    float* out = (float*)d_out;

    k_transpose<<<dim3(32, 32), dim3(32, 8)>>>(w_f);
    k_gather<<<NROWS, 128>>>(word_emb, num_ids, w_alpha, b_alpha);
    k_rank<<<Bq, 128>>>(numbers, num_ids);
    k_group<<<1, 256>>>(is_resp);
    k_prefix<<<dim3(Bq, 4), 256>>>(is_resp);
    k_gemm<<<dim3(8, 17), 256>>>(W_r, b_f, out);
}

// round 4
// speedup vs baseline: 4.3117x; 4.3117x over previous
#include <cuda_runtime.h>
#include <math.h>
#include <stdint.h>

// Problem constants
#define Bq   16
#define Sq   2048
#define Hq   1024
#define Nq   128
#define NROWS (Bq * Nq)          // 2048 rows
#define NPAD  (NROWS + 128)      // padded grouped rows (2176)
#define KX   (5 * Hq)            // 5120: [L0|L1|G0|G1|Init]

// ---------------- scratch (static __device__, no allocation) ----------------
__device__ float g_X[(size_t)NPAD * KX];    // grouped operand rows (tf32-rounded)
__device__ float g_wfT[Hq * Hq];            // w_f^T [n][k], tf32-rounded
__device__ float g_Wrnd[8 * Hq * Hq];       // W_r tf32-rounded [r][n][k]
__device__ float g_alpha[NROWS];
__device__ int   g_perm[NROWS];
__device__ int   g_runstart[NROWS];
__device__ float g_invD[Bq];
__device__ int   g_rowmap[NPAD];            // grouped pos -> original row, -1 = pad
__device__ int   g_slot[NROWS];             // original row -> grouped pos
__device__ int   g_meta[2];                 // {start1, totalTiles}

// ---------------- small device helpers ----------------
__device__ __forceinline__ float tf32r(float x) {
    uint32_t o;
    asm("cvt.rna.tf32.f32 %0, %1;" : "=r"(o) : "f"(x));
    return __uint_as_float(o);
}
__device__ __forceinline__ uint32_t smem_u32(const void* p) {
    uint32_t a;
    asm("{ .reg .u64 t; cvta.to.shared.u64 t, %1; cvt.u32.u64 %0, t; }" : "=r"(a) : "l"(p));
    return a;
}
#define CP16(dst, src) asm volatile("cp.async.cg.shared.global [%0], [%1], 16;" :: "r"(dst), "l"(src) : "memory")
#define CP_COMMIT()    asm volatile("cp.async.commit_group;" ::: "memory")
#define CP_WAIT2()     asm volatile("cp.async.wait_group 2;" ::: "memory")

__device__ __forceinline__ void mma_tf32(float* d, const uint32_t* a, const uint32_t* b) {
    asm volatile("mma.sync.aligned.m16n8k8.row.col.f32.tf32.tf32.f32 "
                 "{%0,%1,%2,%3}, {%4,%5,%6,%7}, {%8,%9}, {%0,%1,%2,%3};"
                 : "+f"(d[0]), "+f"(d[1]), "+f"(d[2]), "+f"(d[3])
                 : "r"(a[0]), "r"(a[1]), "r"(a[2]), "r"(a[3]), "r"(b[0]), "r"(b[1]));
}

// ---------------- K_wf: transpose+round w_f -> g_wfT [n][k] ----------------
__global__ void k_transpose(const float* __restrict__ wf) {
    __shared__ float t[32][33];
    int x0 = blockIdx.x * 32, y0 = blockIdx.y * 32;
    int tx = threadIdx.x, ty = threadIdx.y;          // (32, 8)
    #pragma unroll
    for (int r = 0; r < 32; r += 8)
        t[ty + r][tx] = wf[(size_t)(y0 + ty + r) * Hq + x0 + tx];
    __syncthreads();
    #pragma unroll
    for (int r = 0; r < 32; r += 8)
        g_wfT[(size_t)(x0 + ty + r) * Hq + y0 + tx] = tf32r(t[tx][ty + r]);
}

// ---------------- K_wr: round W_r -> g_Wrnd ----------------
__global__ void k_wrnd(const float* __restrict__ Wr) {
    size_t i = (size_t)blockIdx.x * blockDim.x + threadIdx.x;   // 2M float4s
    const float4* s = (const float4*)Wr;
    float4 v = s[i];
    v.x = tf32r(v.x); v.y = tf32r(v.y); v.z = tf32r(v.z); v.w = tf32r(v.w);
    ((float4*)g_Wrnd)[i] = v;
}

// ---------------- K3: group rows by resp_i + inverse map ----
__global__ void k_group(const int* __restrict__ resp) {
    __shared__ int cls[NROWS];
    __shared__ int offs0[257];
    __shared__ int tcount[256];
    int t = threadIdx.x;                     // 256 threads
    for (int m = t; m < NROWS; m += 256) cls[m] = (resp[m] == 1) ? 1 : 0;
    __syncthreads();
    int c0 = 0;
    #pragma unroll
    for (int k = 0; k < 8; k++) c0 += (cls[t * 8 + k] == 0);
    tcount[t] = c0;
    __syncthreads();
    if (t == 0) {
        int s = 0;
        for (int q = 0; q < 256; q++) { offs0[q] = s; s += tcount[q]; }
        offs0[256] = s;
    }
    __syncthreads();
    int count0 = offs0[256];
    int start1 = ((count0 + 127) / 128) * 128;
    int total1 = NROWS - count0;
    int totalTiles = (start1 + total1 + 127) / 128;
    for (int m = t; m < NPAD; m += 256) g_rowmap[m] = -1;
    __syncthreads();
    int p0 = offs0[t];
    int p1 = start1 + (t * 8 - offs0[t]);
    #pragma unroll
    for (int k = 0; k < 8; k++) {
        int m = t * 8 + k;
        if (cls[m] == 0) { g_rowmap[p0] = m; g_slot[m] = p0; p0++; }
        else             { g_rowmap[p1] = m; g_slot[m] = p1; p1++; }
    }
    if (t == 0) { g_meta[0] = start1; g_meta[1] = totalTiles; }
}

// ---------------- Kz: zero pad rows of g_X ----------------
__global__ void k_zeropad() {
    int pos = blockIdx.x;
    if (g_rowmap[pos] >= 0) return;
    float4* d = (float4*)(g_X + (size_t)pos * KX);
    for (int t = threadIdx.x; t < KX / 4; t += blockDim.x)
        d[t] = make_float4(0.f, 0.f, 0.f, 0.f);
}

// ---------------- K1: gather Init rows (to grouped slot, rounded) + alpha ----
__global__ void k_gather(const float* __restrict__ we, const int* __restrict__ ids,
                         const float* __restrict__ w_alpha, const float* __restrict__ b_alpha) {
    int m = blockIdx.x;                      // original row (b*128+n)
    int b = m >> 7;
    int id = ids[m];
    int idc = min(max(id, 0), Sq - 1);
    int slot = g_slot[m];
    const float4* src = (const float4*)(we + ((size_t)b * Sq + idc) * Hq);
    float4* dst = (float4*)(g_X + (size_t)slot * KX + 4 * Hq);
    const float4* wa = (const float4*)w_alpha;
    float part = 0.f;
    for (int t = threadIdx.x; t < Hq / 4; t += blockDim.x) {
        float4 v = src[t];
        float4 w = wa[t];
        part += v.x * w.x + v.y * w.y + v.z * w.z + v.w * w.w;
        v.x = tf32r(v.x); v.y = tf32r(v.y); v.z = tf32r(v.z); v.w = tf32r(v.w);
        dst[t] = v;
    }
    __shared__ float red[128];
    red[threadIdx.x] = part;
    __syncthreads();
    for (int s = 64; s > 0; s >>= 1) {
        if (threadIdx.x < s) red[threadIdx.x] += red[threadIdx.x + s];
        __syncthreads();
    }
    if (threadIdx.x == 0) {
        float a = 1.f / (1.f + expf(-(red[0] + b_alpha[0])));
        g_alpha[m] = (id >= 0) ? a : 0.f;
    }
}

// ---------------- K2: per-batch stable sort rank + run starts + denom --------
__global__ void k_rank(const float* __restrict__ numbers, const int* __restrict__ ids) {
    int b = blockIdx.x, i = threadIdx.x;
    __shared__ float num[128];
    __shared__ int perm[128];
    __shared__ int validCnt;
    int id = ids[b * 128 + i];
    float x = numbers[b * 128 + i];
    num[i] = x;
    if (i == 0) validCnt = 0;
    __syncthreads();
    int p = 0;
    #pragma unroll 4
    for (int j = 0; j < 128; j++) {
        float y = num[j];
        p += (y < x) || (y == x && j < i);
    }
    perm[p] = i;
    atomicAdd(&validCnt, (id >= 0) ? 1 : 0);
    __syncthreads();
    g_perm[b * 128 + p] = i;
    int node = perm[i];
    int prev = (i > 0) ? perm[i - 1] : 0;
    g_runstart[b * 128 + i] = (i == 0) || (num[node] != num[prev]);
    if (i == 0) g_invD[b] = 1.f / (float)max(validCnt - 1, 1);
}

// ---------------- K4: prefix sums -> slots 0..3 = [L0 L1 G0 G1]*invD (rounded)
__global__ void k_prefix(const int* __restrict__ resp) {
    int b = blockIdx.x;
    int h = blockIdx.y * 256 + threadIdx.x;
    __shared__ float alpha_s[128];
    __shared__ int perm_s[128], rs_s[128], resp_s[128], slot_s[128];
    int t = threadIdx.x;
    if (t < 128) {
        alpha_s[t] = g_alpha[b * 128 + t];
        perm_s[t]  = g_perm[b * 128 + t];
        rs_s[t]    = g_runstart[b * 128 + t];
        resp_s[t]  = resp[b * 128 + t];
        slot_s[t]  = g_slot[b * 128 + t];
    }
    __syncthreads();
    float invD = g_invD[b];
    // pass 1: class totals
    float T0 = 0.f, T1 = 0.f;
    for (int i = 0; i < 128; i++) {
        float u = alpha_s[i] * g_X[(size_t)slot_s[i] * KX + 4 * Hq + h];
        if (resp_s[i]) T1 += u; else T0 += u;
    }
    // pass 2: walk sorted order; snapshot at run starts = strict-less prefix
    float a0 = 0.f, a1 = 0.f, s0 = 0.f, s1 = 0.f;
    for (int p = 0; p < 128; p++) {
        int i = perm_s[p];
        if (rs_s[p]) { s0 = a0; s1 = a1; }
        float u = alpha_s[i] * g_X[(size_t)slot_s[i] * KX + 4 * Hq + h];
        int r = resp_s[i];
        float L0 = s0, L1 = s1;
        float G0 = T0 - L0 - (r ? 0.f : u);
        float G1 = T1 - L1 - (r ? u : 0.f);
        float* Xi = g_X + (size_t)slot_s[i] * KX;
        Xi[0 * Hq + h] = tf32r(L0 * invD);
        Xi[1 * Hq + h] = tf32r(L1 * invD);
        Xi[2 * Hq + h] = tf32r(G0 * invD);
        Xi[3 * Hq + h] = tf32r(G1 * invD);
        if (r) a1 += u; else a0 += u;
    }
}

// ---------------- K5: mma.sync tf32 GEMM  out = relu(X @ Wsel^T + b_f) -------
// BM=128 BN=128 BK=32, 3-stage cp.async pipeline, 8 warps of 32x64.
#define BK      32
#define NKT     (KX / BK)        // 160
#define LDP     36               // padded smem row stride (floats), conflict-free
#define TILE_F  (128 * LDP)      // floats per operand tile (4608)

__global__ void __launch_bounds__(256, 2)
k_gemm(const float* __restrict__ Wr, const float* __restrict__ b_f,
       float* __restrict__ out) {
    int by = blockIdx.y, bx = blockIdx.x;
    if (by >= g_meta[1]) return;

    extern __shared__ float sm[];
    float* As = sm;                    // [3][128][LDP]
    float* Bs = sm + 3 * TILE_F;       // [3][128][LDP]
    int* rows_s = (int*)(sm + 6 * TILE_F);

    int tid = threadIdx.x;
    int wid = tid >> 5, lane = tid & 31;
    int g = lane >> 2, t4 = lane & 3;
    int wm = wid & 3, wn = wid >> 2;    // warp tile: rows wm*32, cols wn*64

    for (int r = tid; r < 128; r += 256) rows_s[r] = g_rowmap[by * 128 + r];

    int ri = (by * 128 >= g_meta[0]) ? 1 : 0;
    const float* wbase[5];
    wbase[0] = Wr + (size_t)(4 + 2 * ri) * Hq * Hq;
    wbase[1] = Wr + (size_t)(5 + 2 * ri) * Hq * Hq;
    wbase[2] = Wr + (size_t)(2 * ri)     * Hq * Hq;
    wbase[3] = Wr + (size_t)(2 * ri + 1) * Hq * Hq;
    wbase[4] = g_wfT;

    // per-thread copy coords: 4 float4 per operand per tile
    int cr[4], cc[4];
    #pragma unroll
    for (int i = 0; i < 4; i++) {
        int idx = tid + i * 256;            // 0..1023
        cr[i] = idx >> 3;                   // row 0..127
        cc[i] = (idx & 7) * 4;              // col 0,4,...,28
    }
    const float* Abase = g_X + (size_t)(by * 128) * KX;

    uint32_t asb = smem_u32(As), bsb = smem_u32(Bs);

    // ---- tile loader ----
    auto load_tile = [&](int kt, int slot) {
        int kk = kt * BK;
        int sl = kk >> 10, hh = kk & 1023;
        const float* wb = wbase[sl];
        #pragma unroll
        for (int i = 0; i < 4; i++) {
            const float* sa = Abase + (size_t)cr[i] * KX + kk + cc[i];
            CP16(asb + (slot * TILE_F + cr[i] * LDP + cc[i]) * 4, sa);
            const float* sb2 = wb + (size_t)(bx * 128 + cr[i]) * Hq + hh + cc[i];
            CP16(bsb + (slot * TILE_F + cr[i] * LDP + cc[i]) * 4, sb2);
        }
    };

    float acc[2][8][4];
    #pragma unroll
    for (int mf = 0; mf < 2; mf++)
        #pragma unroll
        for (int nf = 0; nf < 8; nf++)
            #pragma unroll
            for (int q = 0; q < 4; q++) acc[mf][nf][q] = 0.f;

    load_tile(0, 0); CP_COMMIT();
    load_tile(1, 1); CP_COMMIT();
    load_tile(2, 2); CP_COMMIT();

    for (int kt = 0; kt < NKT; kt++) {
        int slot = kt % 3;
        CP_WAIT2();
        __syncthreads();
        const float* At = As + slot * TILE_F;
        const float* Bt = Bs + slot * TILE_F;
        #pragma unroll
        for (int k8 = 0; k8 < 4; k8++) {
            int kA = k8 * 8 + t4;
            uint32_t a[2][4], b[8][2];
            #pragma unroll
            for (int mf = 0; mf < 2; mf++) {
                const float* ap = At + (wm * 32 + mf * 16 + g) * LDP + kA;
                a[mf][0] = __float_as_uint(ap[0]);
                a[mf][1] = __float_as_uint(ap[8 * LDP]);
                a[mf][2] = __float_as_uint(ap[4]);
                a[mf][3] = __float_as_uint(ap[8 * LDP + 4]);
            }
            #pragma unroll
            for (int nf = 0; nf < 8; nf++) {
                const float* bp = Bt + (wn * 64 + nf * 8 + g) * LDP + kA;
                b[nf][0] = __float_as_uint(bp[0]);
                b[nf][1] = __float_as_uint(bp[4]);
            }
            #pragma unroll
            for (int mf = 0; mf < 2; mf++)
                #pragma unroll
                for (int nf = 0; nf < 8; nf++)
                    mma_tf32(acc[mf][nf], a[mf], b[nf]);
        }
        __syncthreads();
        if (kt + 3 < NKT) load_tile(kt + 3, slot);
        CP_COMMIT();
    }

    // ---- epilogue: bias + relu + scatter rows ----
    #pragma unroll
    for (int mf = 0; mf < 2; mf++) {
        int m0 = wm * 32 + mf * 16 + g;
        int row0 = rows_s[m0];
        int row1 = rows_s[m0 + 8];
        #pragma unroll
        for (int nf = 0; nf < 8; nf++) {
            int col = bx * 128 + wn * 64 + nf * 8 + t4 * 2;
            float bz = b_f[col], bo = b_f[col + 1];
            if (row0 >= 0) {
                float2 v;
                v.x = fmaxf(acc[mf][nf][0] + bz, 0.f);
                v.y = fmaxf(acc[mf][nf][1] + bo, 0.f);
                *(float2*)(out + (size_t)row0 * Hq + col) = v;
            }
            if (row1 >= 0) {
                float2 v;
                v.x = fmaxf(acc[mf][nf][2] + bz, 0.f);
                v.y = fmaxf(acc[mf][nf][3] + bo, 0.f);
                *(float2*)(out + (size_t)row1 * Hq + col) = v;
            }
        }
    }
}

#define SMEM_GEMM (6 * TILE_F * 4 + 512)

// ---------------- launch ----------------
extern "C" void kernel_launch(void* const* d_in, const int* in_sizes, int n_in,
                              void* d_out, int out_size) {
    const float* word_emb  = (const float*)d_in[0];
    const int*   num_ids   = (const int*)  d_in[1];
    const int*   is_resp   = (const int*)  d_in[2];
    const float* numbers   = (const float*)d_in[3];
    const float* w_alpha   = (const float*)d_in[4];
    const float* b_alpha   = (const float*)d_in[5];
    const float* w_f       = (const float*)d_in[6];
    const float* b_f       = (const float*)d_in[7];
    const float* W_r       = (const float*)d_in[8];
    float* out = (float*)d_out;

    void* pW = nullptr;
    cudaGetSymbolAddress(&pW, g_Wrnd);

    k_group<<<1, 256>>>(is_resp);
    k_transpose<<<dim3(32, 32), dim3(32, 8)>>>(w_f);
    k_wrnd<<<8192, 256>>>(W_r);
    k_zeropad<<<NPAD, 256>>>();
    k_gather<<<NROWS, 128>>>(word_emb, num_ids, w_alpha, b_alpha);
    k_rank<<<Bq, 128>>>(numbers, num_ids);
    k_prefix<<<dim3(Bq, 4), 256>>>(is_resp);

    cudaFuncSetAttribute(k_gemm, cudaFuncAttributeMaxDynamicSharedMemorySize, SMEM_GEMM);
    k_gemm<<<dim3(8, 17), 256, SMEM_GEMM>>>((const float*)pW, b_f, out);
}